// round 2
// baseline (speedup 1.0000x reference)
#include <cuda_runtime.h>
#include <cstdint>

// GraphRefiner: 256 graphs x (N=2000 nodes, F=2), shared sparse adjacency (E=7998).
// TAGConv(2->64,K=3) -> relu -> TAGConv(64->2,K=3) + residual.
// Key identity: A (node-space) commutes with W (feature-space), so layer 2 is
// Horner'd in F=2 space and the 64-wide hidden lives only in registers.

#define NNODES 2000
#define EMAX   8192
#define CHUNK  1024
#define NCHMAX 8
#define TPB    256

typedef unsigned long long ull;

// ---- persistent device scratch (no allocations allowed) ----
__device__ int   g_blockcnt[NCHMAX * NNODES];
__device__ int   g_boff[NCHMAX * NNODES];
__device__ int   g_lrank[EMAX];
__device__ int   g_rowptr[NNODES + 1];
__device__ int   g_csr_src[EMAX];
__device__ float g_csr_ew[EMAX];
__device__ float g_csr_norm[EMAX];
__device__ float g_dinv[NNODES];

// ======================= deterministic CSR build =======================

// K1: per 1024-edge chunk (one block), stable per-edge rank within chunk +
// per-(chunk,node) counts. No atomics: match_any within warp, warps serialized.
__global__ void k1_count(const int* __restrict__ col, int E) {
    __shared__ int hist[NNODES];
    int tid = threadIdx.x;
    for (int n = tid; n < NNODES; n += blockDim.x) hist[n] = 0;
    __syncthreads();

    int e = blockIdx.x * CHUNK + tid;
    bool valid = (e < E);
    int c = valid ? col[e] : -1;

    unsigned mask = __match_any_sync(0xffffffffu, c);
    int lane = tid & 31;
    int lr = __popc(mask & ((1u << lane) - 1u));   // rank within group in warp
    int gcount = __popc(mask);
    int wid = tid >> 5;
    int myrank = 0;

    for (int w = 0; w < 32; ++w) {
        if (wid == w) {
            int base = 0;
            if (valid) base = hist[c];
            __syncwarp();
            if (valid && lr == 0) hist[c] = base + gcount;  // group leader
            if (valid) myrank = base + lr;
        }
        __syncthreads();
    }
    if (valid) g_lrank[e] = myrank;
    for (int n = tid; n < NNODES; n += blockDim.x)
        g_blockcnt[blockIdx.x * NNODES + n] = hist[n];
}

// K2: per-node prefix over chunks -> g_boff, degree; block-wide Hillis-Steele
// scan over 2048 -> rowptr.
__global__ void k2_scan(int nchunks) {
    __shared__ int sc[2048];
    int tid = threadIdx.x;
    for (int n = tid; n < NNODES; n += 1024) {
        int run = 0;
        for (int b = 0; b < nchunks; ++b) {
            g_boff[b * NNODES + n] = run;
            run += g_blockcnt[b * NNODES + n];
        }
        sc[n] = run;
    }
    for (int i = tid; i < 2048; i += 1024) if (i >= NNODES) sc[i] = 0;
    __syncthreads();
    int i0 = tid, i1 = tid + 1024;
    for (int off = 1; off < 2048; off <<= 1) {
        int v0 = (i0 >= off) ? sc[i0 - off] : 0;
        int v1 = (i1 >= off) ? sc[i1 - off] : 0;
        __syncthreads();
        sc[i0] += v0; sc[i1] += v1;
        __syncthreads();
    }
    if (tid == 0) g_rowptr[0] = 0;
    if (i0 < NNODES) g_rowptr[i0 + 1] = sc[i0];
    if (i1 < NNODES) g_rowptr[i1 + 1] = sc[i1];
}

// K3: scatter edges to their deterministic CSR slots.
__global__ void k3_fill(const int* __restrict__ row, const int* __restrict__ col,
                        const float* __restrict__ ew, int E) {
    int e = blockIdx.x * blockDim.x + threadIdx.x;
    if (e >= E) return;
    int c = col[e];
    int b = e / CHUNK;
    int p = g_rowptr[c] + g_boff[b * NNODES + c] + g_lrank[e];
    g_csr_src[p] = row[e];
    g_csr_ew[p]  = ew[e];
}

// K4: weighted degree (in CSR order -> deterministic) and dinv.
__global__ void k4_dinv() {
    int n = blockIdx.x * blockDim.x + threadIdx.x;
    if (n >= NNODES) return;
    int s = g_rowptr[n], e = g_rowptr[n + 1];
    float w = 0.f;
    for (int i = s; i < e; ++i) w += g_csr_ew[i];
    g_dinv[n] = (w > 0.f) ? rsqrtf(w) : 0.f;
}

// K5: per-edge norm = dinv[dst] * ew * dinv[src].
__global__ void k5_norm() {
    int n = blockIdx.x * blockDim.x + threadIdx.x;
    if (n >= NNODES) return;
    float di = g_dinv[n];
    int s = g_rowptr[n], e = g_rowptr[n + 1];
    for (int i = s; i < e; ++i)
        g_csr_norm[i] = di * g_csr_ew[i] * g_dinv[g_csr_src[i]];
}

// ======================= main fused kernel =======================

__device__ __forceinline__ ull pack2(float x, float y) {
    ull r; asm("mov.b64 %0, {%1, %2};" : "=l"(r) : "f"(x), "f"(y)); return r;
}
__device__ __forceinline__ void unpack2(ull v, float& x, float& y) {
    asm("mov.b64 {%0, %1}, %2;" : "=f"(x), "=f"(y) : "l"(v));
}
__device__ __forceinline__ void ffma2(ull& d, ull a, ull b) {
    asm("fma.rn.f32x2 %0, %1, %2, %0;" : "+l"(d) : "l"(a), "l"(b));
}

// SMEM layout (bytes)
#define SM_BUF    0                       // 4 x float2[NNODES] = 64000
#define SM_W1     (4 * NNODES * 8)        // 256 x ull = 2048
#define SM_W2     (SM_W1 + 2048)          // 256 x ull = 2048
#define SM_B1     (SM_W2 + 2048)          // 32 x ull  = 256
#define SM_RP     (SM_B1 + 256)           // (NNODES+2) ints = 8008
#define SM_SRC    (SM_RP + (NNODES + 2) * 4)
#define SM_TOTAL  (SM_SRC + EMAX * 2)     // u16 srcs = 16384  -> 92744 total

__device__ __forceinline__ void propagate(const float2* __restrict__ src,
                                          float2* __restrict__ dst,
                                          const int* __restrict__ rp,
                                          const unsigned short* __restrict__ ssrc,
                                          bool accum, int tid) {
    for (int n = tid; n < NNODES; n += TPB) {
        int s = rp[n], e = rp[n + 1];
        float ax, ay;
        if (accum) { float2 t = dst[n]; ax = t.x; ay = t.y; }
        else       { ax = 0.f; ay = 0.f; }
        for (int i = s; i < e; ++i) {
            float w = __ldg(&g_csr_norm[i]);
            float2 v = src[ssrc[i]];
            ax = fmaf(w, v.x, ax);
            ay = fmaf(w, v.y, ay);
        }
        dst[n] = make_float2(ax, ay);
    }
}

extern __shared__ char smem[];

__global__ void __launch_bounds__(TPB, 2) k6_main(
    const float* __restrict__ x,
    const float* __restrict__ W1, const float* __restrict__ b1,
    const float* __restrict__ W2, const float* __restrict__ b2,
    float* __restrict__ out, int E)
{
    float2* B0 = (float2*)(smem + SM_BUF);
    float2* B1v = B0 + NNODES;
    float2* B2v = B1v + NNODES;
    float2* B3v = B2v + NNODES;
    ull* w1p = (ull*)(smem + SM_W1);
    ull* w2p = (ull*)(smem + SM_W2);
    ull* b1p = (ull*)(smem + SM_B1);
    int* rp  = (int*)(smem + SM_RP);
    unsigned short* ssrc = (unsigned short*)(smem + SM_SRC);

    int tid = threadIdx.x;
    int g   = blockIdx.x;

    // ---- stage inputs ----
    const float2* xg = (const float2*)(x + (size_t)g * (2 * NNODES));
    for (int n = tid; n < NNODES; n += TPB) B0[n] = xg[n];
    if (tid < 256) w1p[tid] = ((const ull*)W1)[tid];        // [i=(k*2+f)][j] pairs over j
    if (tid < 256) {                                        // w2p[j*4+k] = (W2[k][j][0], W2[k][j][1])
        int j = tid >> 2, k = tid & 3;
        w2p[tid] = ((const ull*)W2)[(k << 6) + j];
    }
    if (tid < 32) b1p[tid] = ((const ull*)b1)[tid];
    for (int i = tid; i <= NNODES; i += TPB) rp[i] = g_rowptr[i];
    for (int i = tid; i < E; i += TPB) ssrc[i] = (unsigned short)g_csr_src[i];
    float b2x = b2[0], b2y = b2[1];
    __syncthreads();

    // ---- layer-1 hops: z1..z3 ----
    propagate(B0, B1v, rp, ssrc, false, tid); __syncthreads();
    propagate(B1v, B2v, rp, ssrc, false, tid); __syncthreads();
    propagate(B2v, B3v, rp, ssrc, false, tid); __syncthreads();

    // ---- fused dense: h = relu(z*W1cat + b1); y_k = h*W2_k; overwrite in place ----
    for (int n = tid; n < NNODES; n += TPB) {
        float2 z0 = B0[n], z1 = B1v[n], z2 = B2v[n], z3 = B3v[n];
        float zs[8] = { z0.x, z0.y, z1.x, z1.y, z2.x, z2.y, z3.x, z3.y };

        ull h[32];
        #pragma unroll
        for (int j2 = 0; j2 < 32; ++j2) h[j2] = b1p[j2];
        #pragma unroll
        for (int i = 0; i < 8; ++i) {
            ull bz = pack2(zs[i], zs[i]);
            #pragma unroll
            for (int j2 = 0; j2 < 32; ++j2)
                ffma2(h[j2], bz, w1p[i * 32 + j2]);
        }

        ull y[4] = {0ull, 0ull, 0ull, 0ull};
        #pragma unroll
        for (int j2 = 0; j2 < 32; ++j2) {
            float ha, hb; unpack2(h[j2], ha, hb);
            ha = fmaxf(ha, 0.f); hb = fmaxf(hb, 0.f);
            ull ba = pack2(ha, ha), bb = pack2(hb, hb);
            #pragma unroll
            for (int k = 0; k < 4; ++k) {
                ffma2(y[k], ba, w2p[(2 * j2) * 4 + k]);
                ffma2(y[k], bb, w2p[(2 * j2 + 1) * 4 + k]);
            }
        }

        *(ull*)&B3v[n] = y[3];
        *(ull*)&B2v[n] = y[2];
        *(ull*)&B1v[n] = y[1];
        float y0x, y0y; unpack2(y[0], y0x, y0y);
        B0[n] = make_float2(z0.x + y0x + b2x, z0.y + y0y + b2y);  // x + y0 + b2
    }
    __syncthreads();

    // ---- layer-2 Horner: B2+=A*B3; B1+=A*B2; B0+=A*B1 ----
    propagate(B3v, B2v, rp, ssrc, true, tid); __syncthreads();
    propagate(B2v, B1v, rp, ssrc, true, tid); __syncthreads();
    propagate(B1v, B0,  rp, ssrc, true, tid); __syncthreads();

    float2* og = (float2*)(out + (size_t)g * (2 * NNODES));
    for (int n = tid; n < NNODES; n += TPB) og[n] = B0[n];
}

// ======================= host launch =======================

extern "C" void kernel_launch(void* const* d_in, const int* in_sizes, int n_in,
                              void* d_out, int out_size) {
    const float* x  = (const float*)d_in[0];
    const int*   row = (const int*)d_in[1];
    const int*   col = (const int*)d_in[2];
    const float* ew  = (const float*)d_in[3];
    const float* W1  = (const float*)d_in[4];
    const float* b1  = (const float*)d_in[5];
    const float* W2  = (const float*)d_in[6];
    const float* b2  = (const float*)d_in[7];
    float* out = (float*)d_out;

    int E = in_sizes[1];
    int G = out_size / (2 * NNODES);
    int nchunks = (E + CHUNK - 1) / CHUNK;

    cudaFuncSetAttribute(k6_main, cudaFuncAttributeMaxDynamicSharedMemorySize, SM_TOTAL);

    k1_count<<<nchunks, CHUNK>>>(col, E);
    k2_scan<<<1, 1024>>>(nchunks);
    k3_fill<<<(E + 255) / 256, 256>>>(row, col, ew, E);
    k4_dinv<<<(NNODES + 255) / 256, 256>>>();
    k5_norm<<<(NNODES + 255) / 256, 256>>>();
    k6_main<<<G, TPB, SM_TOTAL>>>(x, W1, b1, W2, b2, out, E);
}

// round 5
// speedup vs baseline: 1.0045x; 1.0045x over previous
#include <cuda_runtime.h>
#include <cstdint>

// GraphRefiner: 256 graphs x (N=2000, F=2), shared sparse adjacency (E=7998).
// TAGConv(2->64,K=3) -> relu -> TAGConv(64->2,K=3) + residual.
// A (node-space) commutes with W (feature-space): layer-2 is Horner'd in F=2
// space; the 64-wide hidden lives only in registers. One CTA per graph, all
// node state in SMEM, 2 CTAs/SM -> single wave of 256 CTAs.

#define NNODES 2000
#define EMAX   8192
#define TPB    256
#define BTPB   1024

typedef unsigned long long ull;

// ---- persistent device scratch (no allocations allowed) ----
__device__ int            g_rowptr[NNODES + 1];
__device__ unsigned short g_csr_src16[EMAX];
__device__ float          g_csr_norm[EMAX];

// ======================= fused deterministic CSR build (1 block) =============
// hist -> scan -> atomic fill -> per-node sort by (src, ew-bits) canonicalizes
// the order => bitwise-deterministic CSR and norms, no warp serialization.

__global__ void k_build(const int* __restrict__ row, const int* __restrict__ col,
                        const float* __restrict__ ew, int E) {
    extern __shared__ char bsm[];
    int*            hist = (int*)bsm;                       // 2048 ints
    int*            rp   = hist + 2048;                     // 2048 ints (inclusive scan)
    float*          dinv = (float*)(rp + 2048);             // 2048 floats
    unsigned short* ssrc = (unsigned short*)(dinv + 2048);  // 8192 u16
    float*          sew  = (float*)(ssrc + EMAX);           // 8192 floats

    int tid = threadIdx.x;
    int i0 = tid, i1 = tid + BTPB;

    hist[i0] = 0; hist[i1] = 0;
    __syncthreads();

    // count
    for (int e = tid; e < E; e += BTPB) atomicAdd(&hist[col[e]], 1);
    __syncthreads();

    // inclusive scan over 2048 (Hillis-Steele)
    rp[i0] = hist[i0]; rp[i1] = hist[i1];
    __syncthreads();
    for (int off = 1; off < 2048; off <<= 1) {
        int v0 = (i0 >= off) ? rp[i0 - off] : 0;
        int v1 = (i1 >= off) ? rp[i1 - off] : 0;
        __syncthreads();
        rp[i0] += v0; rp[i1] += v1;
        __syncthreads();
    }

    // cursor = exclusive start
    hist[i0] = i0 ? rp[i0 - 1] : 0;
    hist[i1] = rp[i1 - 1];
    __syncthreads();

    // fill (slot order nondeterministic; sort below canonicalizes)
    for (int e = tid; e < E; e += BTPB) {
        int c = col[e];
        int p = atomicAdd(&hist[c], 1);
        ssrc[p] = (unsigned short)row[e];
        sew[p]  = ew[e];
    }
    __syncthreads();

    // per-node insertion sort by (src, ew-bits); weighted degree in order
    for (int n = tid; n < NNODES; n += BTPB) {
        int s = n ? rp[n - 1] : 0;
        int e = rp[n];
        for (int i = s + 1; i < e; ++i) {
            unsigned short ks = ssrc[i];
            float kw = sew[i];
            unsigned kb = __float_as_uint(kw);
            int j = i - 1;
            while (j >= s) {
                unsigned short js = ssrc[j];
                if (js > ks || (js == ks && __float_as_uint(sew[j]) > kb)) {
                    ssrc[j + 1] = js; sew[j + 1] = sew[j]; --j;
                } else break;
            }
            ssrc[j + 1] = ks; sew[j + 1] = kw;
        }
        float w = 0.f;
        for (int i = s; i < e; ++i) w += sew[i];
        dinv[n] = (w > 0.f) ? rsqrtf(w) : 0.f;
        g_rowptr[n + 1] = e;
    }
    if (tid == 0) g_rowptr[0] = 0;
    __syncthreads();

    // norms + final CSR src
    for (int n = tid; n < NNODES; n += BTPB) {
        int s = n ? rp[n - 1] : 0;
        int e = rp[n];
        float di = dinv[n];
        for (int i = s; i < e; ++i) {
            g_csr_norm[i]  = di * sew[i] * dinv[ssrc[i]];
            g_csr_src16[i] = ssrc[i];
        }
    }
}
#define BUILD_SMEM ((2048 + 2048 + 2048) * 4 + EMAX * 2 + EMAX * 4)

// ======================= main fused kernel ===================================

__device__ __forceinline__ ull pack2(float x, float y) {
    ull r; asm("mov.b64 %0, {%1, %2};" : "=l"(r) : "f"(x), "f"(y)); return r;
}
__device__ __forceinline__ void unpack2(ull v, float& x, float& y) {
    asm("mov.b64 {%0, %1}, %2;" : "=f"(x), "=f"(y) : "l"(v));
}
__device__ __forceinline__ void ffma2(ull& d, ull a, ull b) {
    asm("fma.rn.f32x2 %0, %1, %2, %0;" : "+l"(d) : "l"(a), "l"(b));
}

// SMEM layout (bytes); all 16B-aligned
#define SM_BUF    0                       // 4 x ull[NNODES] = 64000
#define SM_W1     (4 * NNODES * 8)        // 256 ull = 2048
#define SM_W2     (SM_W1 + 2048)          // 256 ull = 2048
#define SM_B1     (SM_W2 + 2048)          // 32 ull  = 256
#define SM_RP     (SM_B1 + 256)           // (NNODES+2) ints = 8008
#define SM_SRC    (SM_RP + (NNODES + 2) * 4)
#define SM_TOTAL  (SM_SRC + EMAX * 2)     // u16 srcs -> 92744 total

__device__ __forceinline__ void propagate(const ull* __restrict__ src,
                                          ull* __restrict__ dst,
                                          const int* __restrict__ rp,
                                          const unsigned short* __restrict__ ssrc,
                                          bool accum, int tid) {
    for (int n = tid; n < NNODES; n += TPB) {
        int s = rp[n], e = rp[n + 1];
        ull acc = accum ? dst[n] : 0ull;
        for (int i = s; i < e; ++i) {
            float w = __ldg(&g_csr_norm[i]);
            ffma2(acc, pack2(w, w), src[ssrc[i]]);
        }
        dst[n] = acc;
    }
}

extern __shared__ char smem[];

__global__ void __launch_bounds__(TPB, 2) k6_main(
    const float* __restrict__ x,
    const float* __restrict__ W1, const float* __restrict__ b1,
    const float* __restrict__ W2, const float* __restrict__ b2,
    float* __restrict__ out, int E)
{
    ull* B0  = (ull*)(smem + SM_BUF);
    ull* B1v = B0 + NNODES;
    ull* B2v = B1v + NNODES;
    ull* B3v = B2v + NNODES;
    ull* w1p = (ull*)(smem + SM_W1);
    ull* w2p = (ull*)(smem + SM_W2);
    ull* b1p = (ull*)(smem + SM_B1);
    int* rp  = (int*)(smem + SM_RP);
    unsigned short* ssrc = (unsigned short*)(smem + SM_SRC);

    int tid = threadIdx.x;
    int g   = blockIdx.x;

    // ---- stage inputs (16B vector copies where possible) ----
    const ulonglong2* xg2 = (const ulonglong2*)(x + (size_t)g * (2 * NNODES));
    ulonglong2* B02 = (ulonglong2*)B0;
    for (int i = tid; i < NNODES / 2; i += TPB) B02[i] = xg2[i];
    if (tid < 256) w1p[tid] = ((const ull*)W1)[tid];   // [i=(k*2+f)] rows of 32 pairs
    if (tid < 256) {                                   // w2p[j*4+k] = (W2[k][j][0], W2[k][j][1])
        int j = tid >> 2, k = tid & 3;
        w2p[tid] = ((const ull*)W2)[(k << 6) + j];
    }
    if (tid < 32) b1p[tid] = ((const ull*)b1)[tid];
    for (int i = tid; i <= NNODES; i += TPB) rp[i] = g_rowptr[i];
    for (int i = tid; i < E; i += TPB) ssrc[i] = g_csr_src16[i];
    float b2x = b2[0], b2y = b2[1];
    __syncthreads();

    // ---- layer-1 hops: z1..z3 ----
    propagate(B0,  B1v, rp, ssrc, false, tid); __syncthreads();
    propagate(B1v, B2v, rp, ssrc, false, tid); __syncthreads();
    propagate(B2v, B3v, rp, ssrc, false, tid); __syncthreads();

    // ---- fused dense: h = relu(z*W1cat + b1); y_k = h*W2_k; overwrite in place ----
    const ulonglong2* w1v = (const ulonglong2*)w1p;
    const ulonglong2* w2v = (const ulonglong2*)w2p;
    const ulonglong2* b1v = (const ulonglong2*)b1p;
    for (int n = tid; n < NNODES; n += TPB) {
        ull z0 = B0[n], z1 = B1v[n], z2 = B2v[n], z3 = B3v[n];
        float zs[8];
        unpack2(z0, zs[0], zs[1]); unpack2(z1, zs[2], zs[3]);
        unpack2(z2, zs[4], zs[5]); unpack2(z3, zs[6], zs[7]);

        ull h[32];
        #pragma unroll
        for (int j4 = 0; j4 < 16; ++j4) {
            ulonglong2 b = b1v[j4];
            h[2 * j4] = b.x; h[2 * j4 + 1] = b.y;
        }
        #pragma unroll
        for (int i = 0; i < 8; ++i) {
            ull bz = pack2(zs[i], zs[i]);
            #pragma unroll
            for (int j4 = 0; j4 < 16; ++j4) {
                ulonglong2 w = w1v[i * 16 + j4];
                ffma2(h[2 * j4],     bz, w.x);
                ffma2(h[2 * j4 + 1], bz, w.y);
            }
        }

        ull y0 = 0, y1 = 0, y2 = 0, y3 = 0;
        #pragma unroll
        for (int j2 = 0; j2 < 32; ++j2) {
            float ha, hb; unpack2(h[j2], ha, hb);
            ha = fmaxf(ha, 0.f); hb = fmaxf(hb, 0.f);
            ull ba = pack2(ha, ha), bb = pack2(hb, hb);
            ulonglong2 wa0 = w2v[(2 * j2) * 2],     wa1 = w2v[(2 * j2) * 2 + 1];
            ulonglong2 wb0 = w2v[(2 * j2 + 1) * 2], wb1 = w2v[(2 * j2 + 1) * 2 + 1];
            ffma2(y0, ba, wa0.x); ffma2(y1, ba, wa0.y);
            ffma2(y2, ba, wa1.x); ffma2(y3, ba, wa1.y);
            ffma2(y0, bb, wb0.x); ffma2(y1, bb, wb0.y);
            ffma2(y2, bb, wb1.x); ffma2(y3, bb, wb1.y);
        }

        B3v[n] = y3;
        B2v[n] = y2;
        B1v[n] = y1;
        float y0x, y0y, zx, zy;
        unpack2(y0, y0x, y0y); unpack2(z0, zx, zy);
        B0[n] = pack2(zx + y0x + b2x, zy + y0y + b2y);   // x + y0 + b2
    }
    __syncthreads();

    // ---- layer-2 Horner: B2+=A*B3; B1+=A*B2; B0+=A*B1 ----
    propagate(B3v, B2v, rp, ssrc, true, tid); __syncthreads();
    propagate(B2v, B1v, rp, ssrc, true, tid); __syncthreads();
    propagate(B1v, B0,  rp, ssrc, true, tid); __syncthreads();

    ulonglong2* og2 = (ulonglong2*)(out + (size_t)g * (2 * NNODES));
    const ulonglong2* B0c = (const ulonglong2*)B0;
    for (int i = tid; i < NNODES / 2; i += TPB) og2[i] = B0c[i];
}

// ======================= host launch =========================================

extern "C" void kernel_launch(void* const* d_in, const int* in_sizes, int n_in,
                              void* d_out, int out_size) {
    const float* x   = (const float*)d_in[0];
    const int*   row = (const int*)d_in[1];
    const int*   col = (const int*)d_in[2];
    const float* ew  = (const float*)d_in[3];
    const float* W1  = (const float*)d_in[4];
    const float* b1  = (const float*)d_in[5];
    const float* W2  = (const float*)d_in[6];
    const float* b2  = (const float*)d_in[7];
    float* out = (float*)d_out;

    int E = in_sizes[1];
    int G = out_size / (2 * NNODES);

    cudaFuncSetAttribute(k_build, cudaFuncAttributeMaxDynamicSharedMemorySize, BUILD_SMEM);
    cudaFuncSetAttribute(k6_main, cudaFuncAttributeMaxDynamicSharedMemorySize, SM_TOTAL);

    k_build<<<1, BTPB, BUILD_SMEM>>>(row, col, ew, E);
    k6_main<<<G, TPB, SM_TOTAL>>>(x, W1, b1, W2, b2, out, E);
}

// round 6
// speedup vs baseline: 1.2351x; 1.2296x over previous
#include <cuda_runtime.h>
#include <cstdint>

// GraphRefiner: 256 graphs x (N=2000, F=2), shared sparse adjacency (E=7998).
// TAGConv(2->64,K=3) -> relu -> TAGConv(64->2,K=3) + residual.
// A (node-space) commutes with W (feature-space): layer-2 is Horner'd in F=2
// space; the 64-wide hidden lives only in registers. One CTA per graph, all
// node state in SMEM, 2 CTAs/SM -> single wave of 256 CTAs.
// R5: dense phase register-tiled (16 tiles x J=4, strip of 4 nodes) so weights
// are loaded once per strip-tile instead of per node -> LDS traffic halved.

#define NNODES 2000
#define EMAX   8192
#define TPB    256
#define BTPB   1024

typedef unsigned long long ull;

// ---- persistent device scratch (no allocations allowed) ----
__device__ int            g_rowptr[NNODES + 1];
__device__ unsigned short g_csr_src16[EMAX];
__device__ float          g_csr_norm[EMAX];

// ======================= fused deterministic CSR build (1 block) =============
__global__ void k_build(const int* __restrict__ row, const int* __restrict__ col,
                        const float* __restrict__ ew, int E) {
    extern __shared__ char bsm[];
    int*            hist = (int*)bsm;                       // 2048 ints
    int*            rp   = hist + 2048;                     // 2048 ints (inclusive scan)
    float*          dinv = (float*)(rp + 2048);             // 2048 floats
    unsigned short* ssrc = (unsigned short*)(dinv + 2048);  // 8192 u16
    float*          sew  = (float*)(ssrc + EMAX);           // 8192 floats

    int tid = threadIdx.x;
    int i0 = tid, i1 = tid + BTPB;

    hist[i0] = 0; hist[i1] = 0;
    __syncthreads();
    for (int e = tid; e < E; e += BTPB) atomicAdd(&hist[col[e]], 1);
    __syncthreads();

    rp[i0] = hist[i0]; rp[i1] = hist[i1];
    __syncthreads();
    for (int off = 1; off < 2048; off <<= 1) {
        int v0 = (i0 >= off) ? rp[i0 - off] : 0;
        int v1 = (i1 >= off) ? rp[i1 - off] : 0;
        __syncthreads();
        rp[i0] += v0; rp[i1] += v1;
        __syncthreads();
    }

    hist[i0] = i0 ? rp[i0 - 1] : 0;
    hist[i1] = rp[i1 - 1];
    __syncthreads();

    for (int e = tid; e < E; e += BTPB) {
        int c = col[e];
        int p = atomicAdd(&hist[c], 1);
        ssrc[p] = (unsigned short)row[e];
        sew[p]  = ew[e];
    }
    __syncthreads();

    // per-node insertion sort by (src, ew-bits) -> canonical order -> bitwise determinism
    for (int n = tid; n < NNODES; n += BTPB) {
        int s = n ? rp[n - 1] : 0;
        int e = rp[n];
        for (int i = s + 1; i < e; ++i) {
            unsigned short ks = ssrc[i];
            float kw = sew[i];
            unsigned kb = __float_as_uint(kw);
            int j = i - 1;
            while (j >= s) {
                unsigned short js = ssrc[j];
                if (js > ks || (js == ks && __float_as_uint(sew[j]) > kb)) {
                    ssrc[j + 1] = js; sew[j + 1] = sew[j]; --j;
                } else break;
            }
            ssrc[j + 1] = ks; sew[j + 1] = kw;
        }
        float w = 0.f;
        for (int i = s; i < e; ++i) w += sew[i];
        dinv[n] = (w > 0.f) ? rsqrtf(w) : 0.f;
        g_rowptr[n + 1] = e;
    }
    if (tid == 0) g_rowptr[0] = 0;
    __syncthreads();

    for (int n = tid; n < NNODES; n += BTPB) {
        int s = n ? rp[n - 1] : 0;
        int e = rp[n];
        float di = dinv[n];
        for (int i = s; i < e; ++i) {
            g_csr_norm[i]  = di * sew[i] * dinv[ssrc[i]];
            g_csr_src16[i] = ssrc[i];
        }
    }
}
#define BUILD_SMEM ((2048 + 2048 + 2048) * 4 + EMAX * 2 + EMAX * 4)

// ======================= main fused kernel ===================================

__device__ __forceinline__ ull pack2(float x, float y) {
    ull r; asm("mov.b64 %0, {%1, %2};" : "=l"(r) : "f"(x), "f"(y)); return r;
}
__device__ __forceinline__ void unpack2(ull v, float& x, float& y) {
    asm("mov.b64 {%0, %1}, %2;" : "=f"(x), "=f"(y) : "l"(v));
}
__device__ __forceinline__ void ffma2(ull& d, ull a, ull b) {
    asm("fma.rn.f32x2 %0, %1, %2, %0;" : "+l"(d) : "l"(a), "l"(b));
}
__device__ __forceinline__ ull add2(ull a, ull b) {
    ull r; asm("add.rn.f32x2 %0, %1, %2;" : "=l"(r) : "l"(a), "l"(b)); return r;
}

// SMEM layout (bytes); all 16B-aligned
#define SM_BUF    0                       // 4 x ull[NNODES] = 64000
#define SM_WTS    (4 * NNODES * 8)        // 544 ull = 4352 (16 tiles x 34 ull)
#define SM_RP     (SM_WTS + 4352)         // (NNODES+2) ints = 8008
#define SM_SRC    (SM_RP + (NNODES + 2) * 4)
#define SM_TOTAL  (SM_SRC + EMAX * 2)     // u16 srcs -> 92744 total

__device__ __forceinline__ void propagate(const ull* __restrict__ src,
                                          ull* __restrict__ dst,
                                          const int* __restrict__ rp,
                                          const unsigned short* __restrict__ ssrc,
                                          bool accum, int tid) {
    for (int n = tid; n < NNODES; n += TPB) {
        int s = rp[n], e = rp[n + 1];
        ull acc0 = accum ? dst[n] : 0ull;
        ull acc1 = 0ull;
        int i = s;
        for (; i + 2 <= e; i += 2) {
            float w0 = __ldg(&g_csr_norm[i]);
            float w1 = __ldg(&g_csr_norm[i + 1]);
            ull v0 = src[ssrc[i]];
            ull v1 = src[ssrc[i + 1]];
            ffma2(acc0, pack2(w0, w0), v0);
            ffma2(acc1, pack2(w1, w1), v1);
        }
        if (i < e) {
            float w0 = __ldg(&g_csr_norm[i]);
            ffma2(acc0, pack2(w0, w0), src[ssrc[i]]);
        }
        dst[n] = add2(acc0, acc1);
    }
}

extern __shared__ char smem[];

__global__ void __launch_bounds__(TPB, 2) k6_main(
    const float* __restrict__ x,
    const float* __restrict__ W1, const float* __restrict__ b1,
    const float* __restrict__ W2, const float* __restrict__ b2,
    float* __restrict__ out, int E)
{
    ull* B0  = (ull*)(smem + SM_BUF);
    ull* B1v = B0 + NNODES;
    ull* B2v = B1v + NNODES;
    ull* B3v = B2v + NNODES;
    ull* wts = (ull*)(smem + SM_WTS);
    int* rp  = (int*)(smem + SM_RP);
    unsigned short* ssrc = (unsigned short*)(smem + SM_SRC);

    int tid = threadIdx.x;
    int g   = blockIdx.x;

    // ---- stage inputs ----
    const ulonglong2* xg2 = (const ulonglong2*)(x + (size_t)g * (2 * NNODES));
    ulonglong2* B02 = (ulonglong2*)B0;
    for (int i = tid; i < NNODES / 2; i += TPB) B02[i] = xg2[i];

    // weights packed per tile t (J=4): [w1t:16][w2t:16][b1t:2] = 34 ull
    //   w1t[i*2+d]  = (W1[i][4t+2d],   W1[i][4t+2d+1])   (i=0..7, d=0..1)
    //   w2t[j*4+q]  = (W2[q][4t+j][0], W2[q][4t+j][1])   (j=0..3, q=0..3)
    //   b1t[d]      = (b1[4t+2d],      b1[4t+2d+1])
    {
        const ull* w1u = (const ull*)W1;
        const ull* w2u = (const ull*)W2;
        const ull* b1u = (const ull*)b1;
        for (int idx = tid; idx < 16 * 34; idx += TPB) {
            int t = idx / 34, r = idx % 34;
            ull v;
            if (r < 16)      { int i = r >> 1, d = r & 1; v = w1u[i * 32 + 2 * t + d]; }
            else if (r < 32) { int rr = r - 16; int j = rr >> 2, q = rr & 3; v = w2u[q * 64 + 4 * t + j]; }
            else             { v = b1u[2 * t + (r - 32)]; }
            wts[idx] = v;
        }
    }
    for (int i = tid; i <= NNODES; i += TPB) rp[i] = g_rowptr[i];
    for (int i = tid; i < E; i += TPB) ssrc[i] = g_csr_src16[i];
    ull b2p = pack2(b2[0], b2[1]);
    __syncthreads();

    // ---- layer-1 hops: z1..z3 ----
    propagate(B0,  B1v, rp, ssrc, false, tid); __syncthreads();
    propagate(B1v, B2v, rp, ssrc, false, tid); __syncthreads();
    propagate(B2v, B3v, rp, ssrc, false, tid); __syncthreads();

    // ---- dense phase: register-tiled. 2 strips x 4 nodes, 16 tiles x J=4 ----
    #pragma unroll 1
    for (int strip = 0; strip < 2; ++strip) {
        int nb = tid + strip * 1024;
        ull y[16];
        #pragma unroll
        for (int c = 0; c < 16; ++c) y[c] = 0ull;

        #pragma unroll 1
        for (int t = 0; t < 16; ++t) {
            ull w1t[16], w2t[16], b1t0, b1t1;
            {
                const ulonglong2* wq = (const ulonglong2*)(wts + t * 34);
                #pragma unroll
                for (int c = 0; c < 8; ++c) { ulonglong2 u = wq[c];     w1t[2*c] = u.x; w1t[2*c+1] = u.y; }
                #pragma unroll
                for (int c = 0; c < 8; ++c) { ulonglong2 u = wq[8 + c]; w2t[2*c] = u.x; w2t[2*c+1] = u.y; }
                ulonglong2 ub = wq[16]; b1t0 = ub.x; b1t1 = ub.y;
            }
            #pragma unroll
            for (int m = 0; m < 4; ++m) {
                int n = nb + (m << 8);
                if (n >= NNODES) n = 0;          // dummy (write suppressed later)
                ull z0 = B0[n], z1 = B1v[n], z2 = B2v[n], z3 = B3v[n];
                float zs[8];
                unpack2(z0, zs[0], zs[1]); unpack2(z1, zs[2], zs[3]);
                unpack2(z2, zs[4], zs[5]); unpack2(z3, zs[6], zs[7]);

                ull h0 = b1t0, h1 = b1t1;
                #pragma unroll
                for (int i = 0; i < 8; ++i) {
                    ull bz = pack2(zs[i], zs[i]);
                    ffma2(h0, bz, w1t[i * 2]);
                    ffma2(h1, bz, w1t[i * 2 + 1]);
                }
                float ha, hb, hc, hd;
                unpack2(h0, ha, hb); unpack2(h1, hc, hd);
                ha = fmaxf(ha, 0.f); hb = fmaxf(hb, 0.f);
                hc = fmaxf(hc, 0.f); hd = fmaxf(hd, 0.f);
                ull d0 = pack2(ha, ha), d1 = pack2(hb, hb);
                ull d2 = pack2(hc, hc), d3 = pack2(hd, hd);
                #pragma unroll
                for (int q = 0; q < 4; ++q) {
                    ull acc = y[m * 4 + q];
                    ffma2(acc, d0, w2t[q]);
                    ffma2(acc, d1, w2t[4 + q]);
                    ffma2(acc, d2, w2t[8 + q]);
                    ffma2(acc, d3, w2t[12 + q]);
                    y[m * 4 + q] = acc;
                }
            }
        }
        // write back: B3=y3, B2=y2, B1=y1, B0 = x + y0 + b2
        #pragma unroll
        for (int m = 0; m < 4; ++m) {
            int n = nb + (m << 8);
            if (n < NNODES) {
                B3v[n] = y[m * 4 + 3];
                B2v[n] = y[m * 4 + 2];
                B1v[n] = y[m * 4 + 1];
                ull z0 = B0[n];
                B0[n] = add2(z0, add2(y[m * 4], b2p));
            }
        }
    }
    __syncthreads();

    // ---- layer-2 Horner: B2+=A*B3; B1+=A*B2; B0+=A*B1 ----
    propagate(B3v, B2v, rp, ssrc, true, tid); __syncthreads();
    propagate(B2v, B1v, rp, ssrc, true, tid); __syncthreads();
    propagate(B1v, B0,  rp, ssrc, true, tid); __syncthreads();

    ulonglong2* og2 = (ulonglong2*)(out + (size_t)g * (2 * NNODES));
    const ulonglong2* B0c = (const ulonglong2*)B0;
    for (int i = tid; i < NNODES / 2; i += TPB) og2[i] = B0c[i];
}

// ======================= host launch =========================================

extern "C" void kernel_launch(void* const* d_in, const int* in_sizes, int n_in,
                              void* d_out, int out_size) {
    const float* x   = (const float*)d_in[0];
    const int*   row = (const int*)d_in[1];
    const int*   col = (const int*)d_in[2];
    const float* ew  = (const float*)d_in[3];
    const float* W1  = (const float*)d_in[4];
    const float* b1  = (const float*)d_in[5];
    const float* W2  = (const float*)d_in[6];
    const float* b2  = (const float*)d_in[7];
    float* out = (float*)d_out;

    int E = in_sizes[1];
    int G = out_size / (2 * NNODES);

    cudaFuncSetAttribute(k_build, cudaFuncAttributeMaxDynamicSharedMemorySize, BUILD_SMEM);
    cudaFuncSetAttribute(k6_main, cudaFuncAttributeMaxDynamicSharedMemorySize, SM_TOTAL);

    k_build<<<1, BTPB, BUILD_SMEM>>>(row, col, ew, E);
    k6_main<<<G, TPB, SM_TOTAL>>>(x, W1, b1, W2, b2, out, E);
}